// round 4
// baseline (speedup 1.0000x reference)
#include <cuda_runtime.h>
#include <cstdint>

// TitansMemory B=16 L=8192 DK=DV=128 — chunked closed-form (T=16).
// Per chunk: parallel GEMM phases (no shuffles) + a scalar serial phase with
// one broadcast-shfl per step. State W,m in SMEM, updated once per chunk.

#define T      16
#define L_SEQ  8192
#define NCH    (L_SEQ / T)
#define DK     128
#define PADK   132    // row stride (floats) for 128-float rows
#define P17    17
#define P33    33

using ull = unsigned long long;

__host__ __device__ constexpr double dpow(double b, int n) {
    double r = 1.0; for (int i = 0; i < n; ++i) r *= b; return r;
}
// step constants (1-based step index)
__host__ __device__ constexpr double Sc(int i) { return -0.1 * dpow(0.9 / 0.98, i); }
__host__ __device__ constexpr double Bc(int i) { return 0.2 / dpow(0.9, i); }
__host__ __device__ constexpr double Ac(int i) { return -0.02 / dpow(0.98, i); }
__host__ __device__ constexpr double Pc(int i) {
    double s = 0.0; for (int k = 1; k <= i; ++k) s += Sc(k); return s;
}
__host__ __device__ constexpr double C16c(int u) { return Ac(u) + Bc(u) * (Pc(16) - Pc(u)); }

__device__ __forceinline__ ull pk(float lo, float hi) {
    ull r; asm("mov.b64 %0,{%1,%2};" : "=l"(r) : "f"(lo), "f"(hi)); return r;
}
__device__ __forceinline__ float hadd2(ull p) {
    float lo, hi; asm("mov.b64 {%0,%1},%2;" : "=f"(lo), "=f"(hi) : "l"(p));
    return lo + hi;
}
__device__ __forceinline__ ull mul2(ull a, ull b) {
    ull d; asm("mul.rn.f32x2 %0,%1,%2;" : "=l"(d) : "l"(a), "l"(b)); return d;
}
__device__ __forceinline__ ull fma2(ull a, ull b, ull c) {
    ull d; asm("fma.rn.f32x2 %0,%1,%2,%3;" : "=l"(d) : "l"(a), "l"(b), "l"(c)); return d;
}
__device__ __forceinline__ ull add2(ull a, ull b) {
    ull d; asm("add.rn.f32x2 %0,%1,%2;" : "=l"(d) : "l"(a), "l"(b)); return d;
}
__device__ __forceinline__ unsigned su32(const void* p) {
    return (unsigned)__cvta_generic_to_shared(p);
}
__device__ __forceinline__ void cp16(unsigned s, const void* g) {
    asm volatile("cp.async.cg.shared.global [%0],[%1],16;" :: "r"(s), "l"(g));
}
__device__ __forceinline__ void cp4(unsigned s, const void* g) {
    asm volatile("cp.async.ca.shared.global [%0],[%1],4;" :: "r"(s), "l"(g));
}
__device__ __forceinline__ void cp_commit() {
    asm volatile("cp.async.commit_group;" ::: "memory");
}
__device__ __forceinline__ void cp_wait_all() {
    asm volatile("cp.async.wait_group 0;" ::: "memory");
}

struct Smem {
    float  Wst[32][PADK];      // rows 0..15: W (true frame), rows 16..31: m
    float  kbuf[2][T][PADK];
    float  qbuf[2][T][PADK];
    float  vbuf[2][T][P17];    // [buf][row j][step i]
    float  d1k[T][P33];        // [t][state row]  = state_row . k_t
    float  d1q[T][P33];
    float  Gs[T][P17];         // [u][t] = k_u . k_t
    float  Hs[T][P17];         // [u][t] = k_u . q_t
    float2 zs[T][P17];         // [row][u] -> (zW, zm)
    float  ys[T][P17];         // [row][step]
};

__global__ __launch_bounds__(512, 1)
void titans_kernel(const float* __restrict__ Q,
                   const float* __restrict__ K,
                   const float* __restrict__ V,
                   float* __restrict__ Y) {
    extern __shared__ char smem_raw[];
    Smem& S = *reinterpret_cast<Smem*>(smem_raw);

    const int tid  = threadIdx.x;
    const int w    = tid >> 5;        // warp 0..15
    const int lane = tid & 31;

    const int b     = blockIdx.x >> 3;
    const int vbase = (blockIdx.x & 7) << 4;

    const size_t base = (size_t)b * L_SEQ * DK;
    const float* gk = K + base;
    const float* gq = Q + base;
    const float* gv = V + base;
    float*       gy = Y + base;

    // zero state
    for (int idx = tid; idx < 32 * PADK; idx += 512)
        ((float*)S.Wst)[idx] = 0.0f;

    // preload chunk 0
    {
        int t = tid >> 5, d = (tid & 31) * 4;
        cp16(su32(&S.kbuf[0][t][d]), gk + t * DK + d);
        cp16(su32(&S.qbuf[0][t][d]), gq + t * DK + d);
        if (tid < 256) {
            int i = tid >> 4, j = tid & 15;
            cp4(su32(&S.vbuf[0][j][i]), gv + (size_t)i * DK + vbase + j);
        }
        cp_commit();
        cp_wait_all();
        __syncthreads();
    }

    for (int chunk = 0; chunk < NCH; ++chunk) {
        const int cur = chunk & 1;
        const int t0  = chunk * T;

        // ---- E: prefetch next chunk ----
        if (chunk + 1 < NCH) {
            const size_t nt = (size_t)(t0 + T) * DK;
            int t = tid >> 5, d = (tid & 31) * 4;
            cp16(su32(&S.kbuf[cur ^ 1][t][d]), gk + nt + t * DK + d);
            cp16(su32(&S.qbuf[cur ^ 1][t][d]), gq + nt + t * DK + d);
            if (tid < 256) {
                int i = tid >> 4, j = tid & 15;
                cp4(su32(&S.vbuf[cur ^ 1][j][i]), gv + nt + (size_t)i * DK + vbase + j);
            }
        }
        cp_commit();

        // ---- A: D1 = state(32x128) . [k_t | q_t]  (warp = t, lane = state row)
        {
            const float* sr = &S.Wst[lane][0];
            const float* kr = &S.kbuf[cur][w][0];
            const float* qr = &S.qbuf[cur][w][0];
            ull ak0 = 0, ak1 = 0, aq0 = 0, aq1 = 0;
            #pragma unroll 8
            for (int d = 0; d < DK; d += 4) {
                ulonglong2 sv = *(const ulonglong2*)(sr + d);
                ulonglong2 kv = *(const ulonglong2*)(kr + d);
                ulonglong2 qv = *(const ulonglong2*)(qr + d);
                ak0 = fma2(sv.x, kv.x, ak0); ak1 = fma2(sv.y, kv.y, ak1);
                aq0 = fma2(sv.x, qv.x, aq0); aq1 = fma2(sv.y, qv.y, aq1);
            }
            S.d1k[w][lane] = hadd2(add2(ak0, ak1));
            S.d1q[w][lane] = hadd2(add2(aq0, aq1));
        }

        // ---- A2: G[u][t] = k_u.k_t, H[u][t] = k_u.q_t (warp = u; lane: t | mat)
        {
            const float* xu = &S.kbuf[cur][w][0];
            const float* xt = (lane < 16) ? &S.kbuf[cur][lane & 15][0]
                                          : &S.qbuf[cur][lane & 15][0];
            ull a0 = 0, a1 = 0;
            #pragma unroll 8
            for (int d = 0; d < DK; d += 4) {
                ulonglong2 uv = *(const ulonglong2*)(xu + d);
                ulonglong2 tv = *(const ulonglong2*)(xt + d);
                a0 = fma2(uv.x, tv.x, a0); a1 = fma2(uv.y, tv.y, a1);
            }
            float g = hadd2(add2(a0, a1));
            if (lane < 16) S.Gs[w][lane] = g;
            else           S.Hs[w][lane & 15] = g;
        }
        __syncthreads();   // bar1

        // ---- B: serial phase (warp = row; lanes 16..31 mirror lanes 0..15)
        {
            const int g = lane & 15;
            float Gc[16], Hc[16];
            #pragma unroll
            for (int u = 0; u < 16; ++u) { Gc[u] = S.Gs[u][g]; Hc[u] = S.Hs[u][g]; }
            float wk = S.d1k[g][w],      mk = S.d1k[g][w + 16];
            float wq = S.d1q[g][w],      mq = S.d1q[g][w + 16];
            const float vv = S.vbuf[cur][w][g];
            float yg = 0.0f, zwg = 0.0f, zmg = 0.0f;

            #pragma unroll
            for (int i = 1; i <= 16; ++i) {
                const float CPi = (float)dpow(0.98, i - 1);
                const float Si  = (float)Sc(i);
                const float Ai  = (float)Ac(i);
                const float Bi  = (float)Bc(i);
                const float CYi = (float)dpow(0.98, i);
                const float ZWi = (float)C16c(i);

                float r = fmaf(CPi, wk, -vv);            // valid in lane i-1
                r = __shfl_sync(0xffffffffu, r, i - 1, 32);
                const float ta = Ai * r, tb = Bi * r;
                wk = fmaf(Si, mk, wk); wk = fmaf(ta, Gc[i - 1], wk);
                mk = fmaf(tb, Gc[i - 1], mk);
                wq = fmaf(Si, mq, wq); wq = fmaf(ta, Hc[i - 1], wq);
                mq = fmaf(tb, Hc[i - 1], mq);
                if (g == i - 1) {
                    yg  = CYi * wq;                      // y_i = c1^i * (What_i . q_i)
                    zwg = ZWi * r;
                    zmg = Bi  * r;
                }
            }
            if (lane < 16) {
                S.ys[w][g] = yg;
                S.zs[w][g] = make_float2(zwg, zmg);
            }
        }
        __syncthreads();   // bar2

        // ---- D: state update + rescale (warp = row; lane = d-block)
        {
            const int d = lane * 4;
            float* Wr = &S.Wst[w][d];
            float* Mr = &S.Wst[w + 16][d];
            ulonglong2 Wv = *(ulonglong2*)Wr;
            ulonglong2 Mv = *(ulonglong2*)Mr;
            const ull P16_2 = pk((float)Pc(16), (float)Pc(16));
            Wv.x = fma2(P16_2, Mv.x, Wv.x);
            Wv.y = fma2(P16_2, Mv.y, Wv.y);
            #pragma unroll
            for (int u = 0; u < 16; ++u) {
                const float2 z = S.zs[w][u];
                ulonglong2 kv = *(const ulonglong2*)&S.kbuf[cur][u][d];
                const ull zw2 = pk(z.x, z.x), zm2 = pk(z.y, z.y);
                Wv.x = fma2(zw2, kv.x, Wv.x); Wv.y = fma2(zw2, kv.y, Wv.y);
                Mv.x = fma2(zm2, kv.x, Mv.x); Mv.y = fma2(zm2, kv.y, Mv.y);
            }
            const float c16f = (float)dpow(0.98, 16);
            const float b16f = (float)dpow(0.9, 16);
            const ull c16s = pk(c16f, c16f), b16s = pk(b16f, b16f);
            Wv.x = mul2(c16s, Wv.x); Wv.y = mul2(c16s, Wv.y);
            Mv.x = mul2(b16s, Mv.x); Mv.y = mul2(b16s, Mv.y);
            *(ulonglong2*)Wr = Wv;
            *(ulonglong2*)Mr = Mv;
        }

        // ---- y writeback ----
        if (tid < 256) {
            int i = tid >> 4, j = tid & 15;
            gy[(size_t)(t0 + i) * DK + vbase + j] = S.ys[j][i];
        }

        cp_wait_all();
        __syncthreads();   // bar3
    }
}

extern "C" void kernel_launch(void* const* d_in, const int* in_sizes, int n_in,
                              void* d_out, int out_size) {
    const float* Q = (const float*)d_in[0];
    const float* K = (const float*)d_in[1];
    const float* V = (const float*)d_in[2];
    float* Y = (float*)d_out;
    (void)in_sizes; (void)n_in; (void)out_size;
    cudaFuncSetAttribute(titans_kernel,
                         cudaFuncAttributeMaxDynamicSharedMemorySize,
                         (int)sizeof(Smem));
    titans_kernel<<<128, 512, sizeof(Smem)>>>(Q, K, V, Y);
}

// round 5
// speedup vs baseline: 13.4024x; 13.4024x over previous
#include <cuda_runtime.h>
#include <cstdint>

// TitansMemory B=16 L=8192 DK=DV=128 — chunked closed-form (T=16).
// Per chunk: parallel GEMM phases (no shuffles) + scalar serial phase with one
// broadcast-shfl per step. State W,m in SMEM, rank-16 update once per chunk.
// R4->R5: all step constants are precomputed FLOAT literals in __constant__
// memory (R4 emitted runtime double-precision dpow loops -> 36ms).

#define T      16
#define L_SEQ  8192
#define NCH    (L_SEQ / T)
#define DK     128
#define PADK   132
#define P17    17
#define P33    33

using ull = unsigned long long;

// step i (1-based) -> index i-1
__constant__ float cCP[16] = {  // 0.98^(i-1)
    1.0f, 0.98f, 0.9604f, 0.941192f, 0.92236816f, 0.9039207968f,
    0.8858423809f, 0.8681255332f, 0.8507630226f, 0.8337477621f,
    0.8170728069f, 0.8007313508f, 0.7847167237f, 0.7690223892f,
    0.7536419414f, 0.7385691035f };
__constant__ float cCY[16] = {  // 0.98^i
    0.98f, 0.9604f, 0.941192f, 0.92236816f, 0.9039207968f, 0.8858423809f,
    0.8681255332f, 0.8507630226f, 0.8337477621f, 0.8170728069f,
    0.8007313508f, 0.7847167237f, 0.7690223892f, 0.7536419414f,
    0.7385691035f, 0.7237977214f };
__constant__ float cS[16] = {   // -0.1*(0.9/0.98)^i
    -0.09183673469f, -0.08433985839f, -0.07745414463f, -0.07113064017f,
    -0.06532344097f, -0.05999029968f, -0.05509252418f, -0.05059456302f,
    -0.04646378542f, -0.04267021926f, -0.03918632342f, -0.03598663375f,
    -0.03304811221f, -0.03034970510f, -0.02787207213f, -0.02559670445f };
__constant__ float cA[16] = {   // -0.02/0.98^i
    -0.02040816327f, -0.02082465640f, -0.02124964939f, -0.02168331570f,
    -0.02212583235f, -0.02257738015f, -0.02303814301f, -0.02350830920f,
    -0.02398807061f, -0.02447762307f, -0.02497716640f, -0.02548690449f,
    -0.02600704540f, -0.02653780143f, -0.02707938921f, -0.02763202981f };
__constant__ float cB[16] = {   // 0.2/0.9^i
    0.2222222222f, 0.2469135802f, 0.2743484225f, 0.3048315805f,
    0.3387017561f, 0.3763352846f, 0.4181503162f, 0.4646114624f,
    0.5162349582f, 0.5735943980f, 0.6373271089f, 0.7081412321f,
    0.7868235912f, 0.8742484347f, 0.9713871497f, 1.0793190552f };
__constant__ float cZW[16] = {  // A(i)+B(i)*(P16-P(i))
    -0.18598573f, -0.18397507f, -0.18127847f, -0.17781047f,
    -0.17347504f, -0.16816631f, -0.16176209f, -0.15414077f,
    -0.14515360f, -0.13463044f, -0.12239474f, -0.10824485f,
    -0.09195752f, -0.07328280f, -0.05194376f, -0.02763203f };

#define P16F  (-0.8369357615f)   // sum of cS[0..15]
#define C16F  (0.7237977214f)    // 0.98^16
#define B16F  (0.1853020189f)    // 0.9^16

__device__ __forceinline__ ull pk(float lo, float hi) {
    ull r; asm("mov.b64 %0,{%1,%2};" : "=l"(r) : "f"(lo), "f"(hi)); return r;
}
__device__ __forceinline__ float hadd2(ull p) {
    float lo, hi; asm("mov.b64 {%0,%1},%2;" : "=f"(lo), "=f"(hi) : "l"(p));
    return lo + hi;
}
__device__ __forceinline__ ull mul2(ull a, ull b) {
    ull d; asm("mul.rn.f32x2 %0,%1,%2;" : "=l"(d) : "l"(a), "l"(b)); return d;
}
__device__ __forceinline__ ull fma2(ull a, ull b, ull c) {
    ull d; asm("fma.rn.f32x2 %0,%1,%2,%3;" : "=l"(d) : "l"(a), "l"(b), "l"(c)); return d;
}
__device__ __forceinline__ ull add2(ull a, ull b) {
    ull d; asm("add.rn.f32x2 %0,%1,%2;" : "=l"(d) : "l"(a), "l"(b)); return d;
}
__device__ __forceinline__ unsigned su32(const void* p) {
    return (unsigned)__cvta_generic_to_shared(p);
}
__device__ __forceinline__ void cp16(unsigned s, const void* g) {
    asm volatile("cp.async.cg.shared.global [%0],[%1],16;" :: "r"(s), "l"(g));
}
__device__ __forceinline__ void cp4(unsigned s, const void* g) {
    asm volatile("cp.async.ca.shared.global [%0],[%1],4;" :: "r"(s), "l"(g));
}
__device__ __forceinline__ void cp_commit() {
    asm volatile("cp.async.commit_group;" ::: "memory");
}
__device__ __forceinline__ void cp_wait_all() {
    asm volatile("cp.async.wait_group 0;" ::: "memory");
}

struct Smem {
    float  Wst[32][PADK];      // rows 0..15: W, rows 16..31: m
    float  kbuf[2][T][PADK];
    float  qbuf[2][T][PADK];
    float  vbuf[2][T][P17];    // [buf][row j][step i]
    float  d1k[T][P33];        // [t][state row]
    float  d1q[T][P33];
    float  Gs[T][P17];         // [u][t] = k_u.k_t
    float  Hs[T][P17];         // [u][t] = k_u.q_t
    float2 zs[T][P17];         // [row][u] -> (zW, zm)
    float  ys[T][P17];         // [row][step]
};

__global__ __launch_bounds__(512, 1)
void titans_kernel(const float* __restrict__ Q,
                   const float* __restrict__ K,
                   const float* __restrict__ V,
                   float* __restrict__ Y) {
    extern __shared__ char smem_raw[];
    Smem& S = *reinterpret_cast<Smem*>(smem_raw);

    const int tid  = threadIdx.x;
    const int w    = tid >> 5;
    const int lane = tid & 31;

    const int b     = blockIdx.x >> 3;
    const int vbase = (blockIdx.x & 7) << 4;

    const size_t base = (size_t)b * L_SEQ * DK;
    const float* gk = K + base;
    const float* gq = Q + base;
    const float* gv = V + base;
    float*       gy = Y + base;

    for (int idx = tid; idx < 32 * PADK; idx += 512)
        ((float*)S.Wst)[idx] = 0.0f;

    {
        int t = tid >> 5, d = (tid & 31) * 4;
        cp16(su32(&S.kbuf[0][t][d]), gk + t * DK + d);
        cp16(su32(&S.qbuf[0][t][d]), gq + t * DK + d);
        if (tid < 256) {
            int i = tid >> 4, j = tid & 15;
            cp4(su32(&S.vbuf[0][j][i]), gv + (size_t)i * DK + vbase + j);
        }
        cp_commit();
        cp_wait_all();
        __syncthreads();
    }

    for (int chunk = 0; chunk < NCH; ++chunk) {
        const int cur = chunk & 1;
        const int t0  = chunk * T;

        // ---- E: prefetch next chunk ----
        if (chunk + 1 < NCH) {
            const size_t nt = (size_t)(t0 + T) * DK;
            int t = tid >> 5, d = (tid & 31) * 4;
            cp16(su32(&S.kbuf[cur ^ 1][t][d]), gk + nt + t * DK + d);
            cp16(su32(&S.qbuf[cur ^ 1][t][d]), gq + nt + t * DK + d);
            if (tid < 256) {
                int i = tid >> 4, j = tid & 15;
                cp4(su32(&S.vbuf[cur ^ 1][j][i]), gv + nt + (size_t)i * DK + vbase + j);
            }
        }
        cp_commit();

        // ---- A: D1 = state(32x128) . [k_t|q_t]  (warp = t, lane = state row)
        {
            const float* sr = &S.Wst[lane][0];
            const float* kr = &S.kbuf[cur][w][0];
            const float* qr = &S.qbuf[cur][w][0];
            ull ak0 = 0, ak1 = 0, aq0 = 0, aq1 = 0;
            #pragma unroll 8
            for (int d = 0; d < DK; d += 4) {
                ulonglong2 sv = *(const ulonglong2*)(sr + d);
                ulonglong2 kv = *(const ulonglong2*)(kr + d);
                ulonglong2 qv = *(const ulonglong2*)(qr + d);
                ak0 = fma2(sv.x, kv.x, ak0); ak1 = fma2(sv.y, kv.y, ak1);
                aq0 = fma2(sv.x, qv.x, aq0); aq1 = fma2(sv.y, qv.y, aq1);
            }
            S.d1k[w][lane] = hadd2(add2(ak0, ak1));
            S.d1q[w][lane] = hadd2(add2(aq0, aq1));
        }

        // ---- A2: G[u][t]=k_u.k_t, H[u][t]=k_u.q_t (warp = u; lane: t|mat)
        {
            const float* xu = &S.kbuf[cur][w][0];
            const float* xt = (lane < 16) ? &S.kbuf[cur][lane & 15][0]
                                          : &S.qbuf[cur][lane & 15][0];
            ull a0 = 0, a1 = 0;
            #pragma unroll 8
            for (int d = 0; d < DK; d += 4) {
                ulonglong2 uv = *(const ulonglong2*)(xu + d);
                ulonglong2 tv = *(const ulonglong2*)(xt + d);
                a0 = fma2(uv.x, tv.x, a0); a1 = fma2(uv.y, tv.y, a1);
            }
            float g = hadd2(add2(a0, a1));
            if (lane < 16) S.Gs[w][lane] = g;
            else           S.Hs[w][lane & 15] = g;
        }
        __syncthreads();

        // ---- B: serial phase (warp = row; lanes 16..31 mirror 0..15)
        {
            const int g = lane & 15;
            float Gc[16], Hc[16];
            #pragma unroll
            for (int u = 0; u < 16; ++u) { Gc[u] = S.Gs[u][g]; Hc[u] = S.Hs[u][g]; }
            float wk = S.d1k[g][w], mk = S.d1k[g][w + 16];
            float wq = S.d1q[g][w], mq = S.d1q[g][w + 16];
            const float vv = S.vbuf[cur][w][g];
            float yg = 0.0f, zwg = 0.0f, zmg = 0.0f;

            #pragma unroll
            for (int i = 0; i < 16; ++i) {
                float r = fmaf(cCP[i], wk, -vv);          // valid in lane i
                r = __shfl_sync(0xffffffffu, r, i, 32);
                const float ta = cA[i] * r, tb = cB[i] * r;
                wk = fmaf(cS[i], mk, wk); wk = fmaf(ta, Gc[i], wk);
                mk = fmaf(tb, Gc[i], mk);
                wq = fmaf(cS[i], mq, wq); wq = fmaf(ta, Hc[i], wq);
                mq = fmaf(tb, Hc[i], mq);
                if (g == i) {
                    yg  = cCY[i] * wq;
                    zwg = cZW[i] * r;
                    zmg = cB[i]  * r;
                }
            }
            if (lane < 16) {
                S.ys[w][g] = yg;
                S.zs[w][g] = make_float2(zwg, zmg);
            }
        }
        __syncthreads();

        // ---- D: state update + rescale (warp = row; lane = d-block)
        {
            const int d = lane * 4;
            float* Wr = &S.Wst[w][d];
            float* Mr = &S.Wst[w + 16][d];
            ulonglong2 Wv = *(ulonglong2*)Wr;
            ulonglong2 Mv = *(ulonglong2*)Mr;
            const ull P16_2 = pk(P16F, P16F);
            Wv.x = fma2(P16_2, Mv.x, Wv.x);
            Wv.y = fma2(P16_2, Mv.y, Wv.y);
            #pragma unroll
            for (int u = 0; u < 16; ++u) {
                const float2 z = S.zs[w][u];
                ulonglong2 kv = *(const ulonglong2*)&S.kbuf[cur][u][d];
                const ull zw2 = pk(z.x, z.x), zm2 = pk(z.y, z.y);
                Wv.x = fma2(zw2, kv.x, Wv.x); Wv.y = fma2(zw2, kv.y, Wv.y);
                Mv.x = fma2(zm2, kv.x, Mv.x); Mv.y = fma2(zm2, kv.y, Mv.y);
            }
            const ull c16s = pk(C16F, C16F), b16s = pk(B16F, B16F);
            Wv.x = mul2(c16s, Wv.x); Wv.y = mul2(c16s, Wv.y);
            Mv.x = mul2(b16s, Mv.x); Mv.y = mul2(b16s, Mv.y);
            *(ulonglong2*)Wr = Wv;
            *(ulonglong2*)Mr = Mv;
        }

        // ---- y writeback ----
        if (tid < 256) {
            int i = tid >> 4, j = tid & 15;
            gy[(size_t)(t0 + i) * DK + vbase + j] = S.ys[j][i];
        }

        cp_wait_all();
        __syncthreads();
    }
}

extern "C" void kernel_launch(void* const* d_in, const int* in_sizes, int n_in,
                              void* d_out, int out_size) {
    const float* Q = (const float*)d_in[0];
    const float* K = (const float*)d_in[1];
    const float* V = (const float*)d_in[2];
    float* Y = (float*)d_out;
    (void)in_sizes; (void)n_in; (void)out_size;
    cudaFuncSetAttribute(titans_kernel,
                         cudaFuncAttributeMaxDynamicSharedMemorySize,
                         (int)sizeof(Smem));
    titans_kernel<<<128, 512, sizeof(Smem)>>>(Q, K, V, Y);
}

// round 6
// speedup vs baseline: 18.8144x; 1.4038x over previous
#include <cuda_runtime.h>
#include <cstdint>

// TitansMemory B=16 L=8192 DK=DV=128.
// Direct delta-rule recurrence, rescaled state (R2 math, validated):
//   What = W / c1^t, mhat = m / beta^t  -> per-step update is 3 fma2/pair,
//   all decay constants are compile-time immediates.
// 2048 (b,v) row-chains; 1 warp per chain; 256 CTAs x 8 warps -> 16 warps/SM.
// k/q/v double-buffered in SMEM via cp.async (16-step chunks).

#define CSTEPS 16
#define L_SEQ  8192
#define NCH    (L_SEQ / CSTEPS)
#define DK     128

using ull = unsigned long long;

__device__ __forceinline__ ull pk(float lo, float hi) {
    ull r; asm("mov.b64 %0,{%1,%2};" : "=l"(r) : "f"(lo), "f"(hi)); return r;
}
__device__ __forceinline__ float hadd2(ull p) {
    float lo, hi; asm("mov.b64 {%0,%1},%2;" : "=f"(lo), "=f"(hi) : "l"(p));
    return lo + hi;
}
__device__ __forceinline__ ull mul2(ull a, ull b) {
    ull d; asm("mul.rn.f32x2 %0,%1,%2;" : "=l"(d) : "l"(a), "l"(b)); return d;
}
__device__ __forceinline__ ull fma2(ull a, ull b, ull c) {
    ull d; asm("fma.rn.f32x2 %0,%1,%2,%3;" : "=l"(d) : "l"(a), "l"(b), "l"(c)); return d;
}
__device__ __forceinline__ unsigned su32(const void* p) {
    return (unsigned)__cvta_generic_to_shared(p);
}
__device__ __forceinline__ void cp16(unsigned s, const void* g) {
    asm volatile("cp.async.cg.shared.global [%0],[%1],16;" :: "r"(s), "l"(g));
}
__device__ __forceinline__ void cp4(unsigned s, const void* g) {
    asm volatile("cp.async.ca.shared.global [%0],[%1],4;" :: "r"(s), "l"(g));
}
__device__ __forceinline__ void cp_commit() {
    asm volatile("cp.async.commit_group;" ::: "memory");
}
__device__ __forceinline__ void cp_wait_all() {
    asm volatile("cp.async.wait_group 0;" ::: "memory");
}

__global__ __launch_bounds__(256, 2)
void titans_kernel(const float* __restrict__ Q,
                   const float* __restrict__ K,
                   const float* __restrict__ V,
                   float* __restrict__ Y) {
    // compile-time step constants (index i = step within chunk, 0-based)
    static constexpr float cCP[16] = {  // 0.98^i
        1.0f, 0.98f, 0.9604f, 0.941192f, 0.92236816f, 0.9039207968f,
        0.8858423809f, 0.8681255332f, 0.8507630226f, 0.8337477621f,
        0.8170728069f, 0.8007313508f, 0.7847167237f, 0.7690223892f,
        0.7536419414f, 0.7385691035f };
    static constexpr float cCY[16] = {  // 0.98^(i+1)
        0.98f, 0.9604f, 0.941192f, 0.92236816f, 0.9039207968f, 0.8858423809f,
        0.8681255332f, 0.8507630226f, 0.8337477621f, 0.8170728069f,
        0.8007313508f, 0.7847167237f, 0.7690223892f, 0.7536419414f,
        0.7385691035f, 0.7237977214f };
    static constexpr float cS[16] = {   // -0.1*(0.9/0.98)^(i+1)
        -0.09183673469f, -0.08433985839f, -0.07745414463f, -0.07113064017f,
        -0.06532344097f, -0.05999029968f, -0.05509252418f, -0.05059456302f,
        -0.04646378542f, -0.04267021926f, -0.03918632342f, -0.03598663375f,
        -0.03304811221f, -0.03034970510f, -0.02787207213f, -0.02559670445f };
    static constexpr float cA[16] = {   // -0.02/0.98^(i+1)
        -0.02040816327f, -0.02082465640f, -0.02124964939f, -0.02168331570f,
        -0.02212583235f, -0.02257738015f, -0.02303814301f, -0.02350830920f,
        -0.02398807061f, -0.02447762307f, -0.02497716640f, -0.02548690449f,
        -0.02600704540f, -0.02653780143f, -0.02707938921f, -0.02763202981f };
    static constexpr float cB[16] = {   // 0.2/0.9^(i+1)
        0.2222222222f, 0.2469135802f, 0.2743484225f, 0.3048315805f,
        0.3387017561f, 0.3763352846f, 0.4181503162f, 0.4646114624f,
        0.5162349582f, 0.5735943980f, 0.6373271089f, 0.7081412321f,
        0.7868235912f, 0.8742484347f, 0.9713871497f, 1.0793190552f };
    constexpr float C16F = 0.7237977214f;   // 0.98^16
    constexpr float B16F = 0.1853020189f;   // 0.9^16

    __shared__ float kq[2][2][CSTEPS][DK];   // [buf][k/q][t][d]
    __shared__ float vT[2][8][20];           // [buf][row][t]
    __shared__ float yb[2][CSTEPS][8];       // [buf][t][row]

    const int tid  = threadIdx.x;
    const int w    = tid >> 5;               // warp 0..7 -> row
    const int lane = tid & 31;

    const int b     = blockIdx.x >> 4;       // 16 batches
    const int vbase = (blockIdx.x & 15) << 3;// 16 groups x 8 rows

    const size_t base = (size_t)b * L_SEQ * DK;
    const float* gk = K + base;
    const float* gq = Q + base;
    const float* gv = V + base;
    float*       gy = Y + base;

    // state: lane owns What[row, 4*lane..+3], mhat same
    ull W01 = 0, W23 = 0, M01 = 0, M23 = 0;

    // ---- preload chunk 0 ----
    {
        #pragma unroll
        for (int u = 0; u < 2; ++u) {
            cp16(su32(&kq[0][0][0][0]) + (u * 256 + tid) * 16, gk + (u * 256 + tid) * 4);
            cp16(su32(&kq[0][1][0][0]) + (u * 256 + tid) * 16, gq + (u * 256 + tid) * 4);
        }
        if (tid < 128) {
            int t = tid >> 3, j = tid & 7;
            cp4(su32(&vT[0][j][0]) + t * 4, gv + (size_t)t * DK + vbase + j);
        }
        cp_commit();
        cp_wait_all();
        __syncthreads();
    }

    for (int chunk = 0; chunk < NCH; ++chunk) {
        const int cur = chunk & 1;
        const int t0  = chunk * CSTEPS;

        // prefetch next chunk
        if (chunk + 1 < NCH) {
            const int nb = cur ^ 1;
            const size_t nt = (size_t)(t0 + CSTEPS) * DK;
            #pragma unroll
            for (int u = 0; u < 2; ++u) {
                cp16(su32(&kq[nb][0][0][0]) + (u * 256 + tid) * 16, gk + nt + (u * 256 + tid) * 4);
                cp16(su32(&kq[nb][1][0][0]) + (u * 256 + tid) * 16, gq + nt + (u * 256 + tid) * 4);
            }
            if (tid < 128) {
                int t = tid >> 3, j = tid & 7;
                cp4(su32(&vT[nb][j][0]) + t * 4, gv + nt + (size_t)t * DK + vbase + j);
            }
        }
        cp_commit();

        // ---- 16 sequential steps ----
        #pragma unroll
        for (int i = 0; i < CSTEPS; ++i) {
            const float4 k4 = *(const float4*)&kq[cur][0][i][lane << 2];
            const float4 q4 = *(const float4*)&kq[cur][1][i][lane << 2];
            const ull k01 = pk(k4.x, k4.y), k23 = pk(k4.z, k4.w);
            const ull q01 = pk(q4.x, q4.y), q23 = pk(q4.z, q4.w);

            // D1 = What_pre . k
            float D1 = hadd2(fma2(W01, k01, mul2(W23, k23)));
            #pragma unroll
            for (int off = 16; off; off >>= 1)
                D1 += __shfl_xor_sync(0xffffffffu, D1, off);

            const float vv = vT[cur][w][i];
            const float r  = fmaf(cCP[i], D1, -vv);
            const float ar = cA[i] * r;
            const float br = cB[i] * r;
            const ull a2 = pk(ar, ar);
            const ull b2 = pk(br, br);
            const ull s2 = pk(cS[i], cS[i]);

            // What += s*mhat + a*k ;  mhat += b*k
            W01 = fma2(s2, M01, W01); W01 = fma2(a2, k01, W01); M01 = fma2(b2, k01, M01);
            W23 = fma2(s2, M23, W23); W23 = fma2(a2, k23, W23); M23 = fma2(b2, k23, M23);

            // y = c1^(i+1) * (What_post . q)
            float D2 = hadd2(fma2(W01, q01, mul2(W23, q23)));
            #pragma unroll
            for (int off = 16; off; off >>= 1)
                D2 += __shfl_xor_sync(0xffffffffu, D2, off);
            if (lane == 0)
                yb[cur][i][w] = cCY[i] * D2;
        }

        // rescale back to chunk-local frame
        {
            const ull c16 = pk(C16F, C16F);
            const ull b16 = pk(B16F, B16F);
            W01 = mul2(c16, W01); W23 = mul2(c16, W23);
            M01 = mul2(b16, M01); M23 = mul2(b16, M23);
        }

        cp_wait_all();
        __syncthreads();

        // write back this chunk's outputs
        if (tid < 128) {
            int i = tid >> 3, j = tid & 7;
            gy[(size_t)(t0 + i) * DK + vbase + j] = yb[cur][i][j];
        }
    }
}

extern "C" void kernel_launch(void* const* d_in, const int* in_sizes, int n_in,
                              void* d_out, int out_size) {
    const float* Q = (const float*)d_in[0];
    const float* K = (const float*)d_in[1];
    const float* V = (const float*)d_in[2];
    float* Y = (float*)d_out;
    (void)in_sizes; (void)n_in; (void)out_size;
    titans_kernel<<<256, 256>>>(Q, K, V, Y);
}